// round 13
// baseline (speedup 1.0000x reference)
#include <cuda_runtime.h>
#include <cstdint>

#define L_SEQ  50
#define BATCH  256
#define DIN    256
#define LAT    512
#define HODE   1024
#define HID    1024
#define DSTRIDE 257
#define JC     3072
#define OUT2_OFF (L_SEQ*BATCH*LAT)
#define NB     256

// ---- persistent scratch ----
__device__ float g_S0[BATCH*LAT];
__device__ float g_S1[BATCH*LAT];
__device__ float g_Y [BATCH*LAT];
__device__ float g_Z [BATCH*HODE];
__device__ float g_Gp[4][BATCH*HID];      // gate streams: r, z, nx, nh
__device__ float g_W1c [LAT*HODE];        // tf32-rounded weights (immutable -> L1)
__device__ float g_W2c [HODE*LAT];
__device__ float g_WihTc[DIN*JC];
__device__ float g_WhhTc[HID*JC];

// ---- tree barrier state (monotonic counters -> replay-safe; no fences -> no L1 flush) ----
__device__ unsigned g_c1[16*32];          // one counter per 128B line
__device__ unsigned g_c0;
__device__ unsigned g_sense;

__device__ __forceinline__ void gridbar(int b){
    __syncthreads();
    if (threadIdx.x == 0){
        unsigned s;
        asm volatile("ld.acquire.gpu.u32 %0, [%1];" : "=r"(s) : "l"(&g_sense) : "memory");
        unsigned o1;
        asm volatile("atom.add.acq_rel.gpu.u32 %0, [%1], 1;"
                     : "=r"(o1) : "l"(&g_c1[(b>>4)*32]) : "memory");
        if ((o1 & 15u) == 15u){
            unsigned o0;
            asm volatile("atom.add.acq_rel.gpu.u32 %0, [%1], 1;"
                         : "=r"(o0) : "l"(&g_c0) : "memory");
            if ((o0 & 15u) == 15u){
                asm volatile("st.release.gpu.u32 [%0], %1;" :: "l"(&g_sense), "r"(s+1u) : "memory");
            } else {
                unsigned v;
                do { asm volatile("ld.acquire.gpu.u32 %0, [%1];" : "=r"(v) : "l"(&g_sense) : "memory"); } while (v == s);
            }
        } else {
            unsigned v;
            do { asm volatile("ld.acquire.gpu.u32 %0, [%1];" : "=r"(v) : "l"(&g_sense) : "memory"); } while (v == s);
        }
    }
    __syncthreads();
}

__device__ __forceinline__ float tf32r(float x){
    uint32_t u; asm("cvt.rna.tf32.f32 %0, %1;" : "=r"(u) : "f"(x));
    return __uint_as_float(u);
}
__device__ __forceinline__ float fsigmoid(float x){ return 1.0f/(1.0f + __expf(-x)); }
__device__ __forceinline__ float ftanh(float x){ return 1.0f - 2.0f/(__expf(2.0f*x) + 1.0f); }

__device__ __forceinline__ void mma8(float (&d)[4], const uint32_t (&a)[4], const uint32_t (&b)[2]){
    asm volatile("mma.sync.aligned.m16n8k8.row.col.f32.tf32.tf32.f32 "
        "{%0,%1,%2,%3}, {%4,%5,%6,%7}, {%8,%9}, {%0,%1,%2,%3};"
        : "+f"(d[0]),"+f"(d[1]),"+f"(d[2]),"+f"(d[3])
        : "r"(a[0]),"r"(a[1]),"r"(a[2]),"r"(a[3]), "r"(b[0]),"r"(b[1]));
}

// smem geometry: A buffer 64 rows x 72 (two 32-k permuted subtiles, pad 36 each)
//                B buffer 64 k-rows x 36 (32 n cols + pad)
#define A_BUF (64*72)
#define B_BUF (64*36)
#define SMEM_FLOATS (2*A_BUF + 2*B_BUF)

// compute one 64x32x64 tile step: d[mi][4], warp tile 32x8
__device__ __forceinline__ void compute64(const float* __restrict__ A,
                                          const float* __restrict__ B,
                                          int wm, int wn, int g, int t4,
                                          float (&d)[2][4])
{
    const int nc = wn*8 + g;
    #pragma unroll
    for (int sub = 0; sub < 2; sub++){
        float Ar[4][8];
        #pragma unroll
        for (int rr = 0; rr < 4; rr++){
            const float* p = A + (wm*32 + rr*8 + g)*72 + sub*36 + t4*8;
            float4 h0 = *(const float4*)p;
            float4 h1 = *(const float4*)(p+4);
            Ar[rr][0]=h0.x; Ar[rr][1]=h0.y; Ar[rr][2]=h0.z; Ar[rr][3]=h0.w;
            Ar[rr][4]=h1.x; Ar[rr][5]=h1.y; Ar[rr][6]=h1.z; Ar[rr][7]=h1.w;
        }
        #pragma unroll
        for (int ks = 0; ks < 4; ks++){
            uint32_t bb[2] = { __float_as_uint(B[(sub*32 + ks*8 + t4)*36 + nc]),
                               __float_as_uint(B[(sub*32 + ks*8 + t4 + 4)*36 + nc]) };
            #pragma unroll
            for (int mi = 0; mi < 2; mi++){
                uint32_t a[4] = { __float_as_uint(Ar[2*mi  ][2*ks  ]),
                                  __float_as_uint(Ar[2*mi+1][2*ks  ]),
                                  __float_as_uint(Ar[2*mi  ][2*ks+1]),
                                  __float_as_uint(Ar[2*mi+1][2*ks+1]) };
                mma8(d[mi], a, bb);
            }
        }
    }
}

// stage 16 A-values (contiguous k) into permuted layout
__device__ __forceinline__ void stageA64(float* Abuf, int am, int subs, int kk0, const float* va){
    float* rowp = Abuf + am*72 + subs*36;
    #pragma unroll
    for (int j = 0; j < 16; j++){
        const int kk = kk0 + j;
        rowp[(kk&3)*8 + (kk>>2)] = va[j];
    }
}

// ---- setup kernels ----
__global__ __launch_bounds__(256) void k_cvt4(const float* __restrict__ in,
                                              float* __restrict__ out, int n4)
{
    int i = blockIdx.x*256 + threadIdx.x;
    if (i >= n4) return;
    float4 v = *(const float4*)&in[i*4];
    v.x = tf32r(v.x); v.y = tf32r(v.y); v.z = tf32r(v.z); v.w = tf32r(v.w);
    *(float4*)&out[i*4] = v;
}

__global__ __launch_bounds__(256) void k_transpose(const float* __restrict__ W, int K,
                                                   float* __restrict__ WT)
{
    __shared__ float tile[32][33];
    const int j0 = blockIdx.x*32, k0 = blockIdx.y*32;
    const int r = threadIdx.x >> 3, c4 = (threadIdx.x & 7)*4;
    float4 v = *(const float4*)&W[(size_t)(j0+r)*K + k0 + c4];
    tile[r][c4+0]=v.x; tile[r][c4+1]=v.y; tile[r][c4+2]=v.z; tile[r][c4+3]=v.w;
    __syncthreads();
    float4 o = make_float4(tf32r(tile[c4+0][r]), tf32r(tile[c4+1][r]),
                           tf32r(tile[c4+2][r]), tf32r(tile[c4+3][r]));
    *(float4*)&WT[(size_t)(k0+r)*JC + j0 + c4] = o;
}

// ==================== THE persistent kernel ====================
__global__ __launch_bounds__(256, 2) void k_main(const float* __restrict__ data,
                                                 const float* __restrict__ b1,
                                                 const float* __restrict__ b2,
                                                 const float* __restrict__ bih,
                                                 const float* __restrict__ bhh,
                                                 float* __restrict__ out)
{
    extern __shared__ float smem[];
    float* Asb[2] = { smem, smem + A_BUF };
    float* Bsb[2] = { smem + 2*A_BUF, smem + 2*A_BUF + B_BUF };

    const int tid = threadIdx.x;
    const int b   = blockIdx.x;
    const int lane = tid & 31, warp = tid >> 5;
    const int wm = warp >> 2, wn = warp & 3;
    const int g = lane >> 2, t4 = lane & 3;
    const int lane4 = tid & 3;
    const int am = tid >> 2, subs = lane4 >> 1, kk0s = (lane4 & 1)*16;
    const int bk2 = tid >> 2, bn8 = lane4*8;

    // zero initial state
    {
        const int e0 = b*(BATCH*LAT/NB) + tid*2;
        __stcg((float2*)&g_S0[e0], make_float2(0.f, 0.f));
    }
    gridbar(b);

    for (int t = 0; t < L_SEQ; t++){
        float* Sr = (t & 1) ? g_S1 : g_S0;
        float* Sw = (t & 1) ? g_S0 : g_S1;
        const int J = (t == L_SEQ-1) ? HID : LAT;
        const float* base = Sr;

        for (int s = 0; s < 3; s++){
            // ===== phase A: Z = tanh(base @ W1 + b1); 128 blocks, KT=8 =====
            if (b < 128){
                const int n0 = (b & 31)*32, m0 = (b >> 5)*64;
                float d[2][4] = {{0.f,0.f,0.f,0.f},{0.f,0.f,0.f,0.f}};
                float va[16]; float4 vb0, vb1;
                auto LDG = [&](int kt){
                    const float* pa = base + (size_t)(m0+am)*LAT + kt*64 + lane4*16;
                    float4 x0 = __ldcg((const float4*)pa);
                    float4 x1 = __ldcg((const float4*)(pa+4));
                    float4 x2 = __ldcg((const float4*)(pa+8));
                    float4 x3 = __ldcg((const float4*)(pa+12));
                    va[0]=tf32r(x0.x); va[1]=tf32r(x0.y); va[2]=tf32r(x0.z); va[3]=tf32r(x0.w);
                    va[4]=tf32r(x1.x); va[5]=tf32r(x1.y); va[6]=tf32r(x1.z); va[7]=tf32r(x1.w);
                    va[8]=tf32r(x2.x); va[9]=tf32r(x2.y); va[10]=tf32r(x2.z); va[11]=tf32r(x2.w);
                    va[12]=tf32r(x3.x); va[13]=tf32r(x3.y); va[14]=tf32r(x3.z); va[15]=tf32r(x3.w);
                    const float* pb = g_W1c + (size_t)(kt*64 + bk2)*HODE + n0 + bn8;
                    vb0 = *(const float4*)pb; vb1 = *(const float4*)(pb+4);
                };
                auto STS = [&](int c){
                    stageA64(Asb[c], am, subs, kk0s, va);
                    float* qd = Bsb[c] + bk2*36 + bn8;
                    *(float4*)qd = vb0; *(float4*)(qd+4) = vb1;
                };
                LDG(0); STS(0); LDG(1); __syncthreads();
                for (int kt = 0; kt < 8; kt++){
                    const int c = kt & 1;
                    if (kt+1 < 8) STS(c^1);
                    if (kt+2 < 8) LDG(kt+2);
                    compute64(Asb[c], Bsb[c], wm, wn, g, t4, d);
                    __syncthreads();
                }
                #pragma unroll
                for (int mi = 0; mi < 2; mi++){
                    const int r0 = m0 + wm*32 + mi*16 + g;
                    const int c  = n0 + wn*8 + t4*2;
                    const float c0 = b1[c], c1 = b1[c+1];
                    __stcg((float2*)&g_Z[(size_t)r0*HODE + c],
                           make_float2(ftanh(d[mi][0]+c0), ftanh(d[mi][1]+c1)));
                    __stcg((float2*)&g_Z[(size_t)(r0+8)*HODE + c],
                           make_float2(ftanh(d[mi][2]+c0), ftanh(d[mi][3]+c1)));
                }
            }
            gridbar(b);

            // ===== phase B: Y = base + (Z @ W2 + b2)*h; 64 blocks, KT=16 =====
            if (b < 64){
                const int n0 = (b & 15)*32, m0 = (b >> 4)*64;
                float d[2][4] = {{0.f,0.f,0.f,0.f},{0.f,0.f,0.f,0.f}};
                float va[16]; float4 vb0, vb1;
                auto LDG = [&](int kt){
                    const float* pa = g_Z + (size_t)(m0+am)*HODE + kt*64 + lane4*16;
                    float4 x0 = __ldcg((const float4*)pa);
                    float4 x1 = __ldcg((const float4*)(pa+4));
                    float4 x2 = __ldcg((const float4*)(pa+8));
                    float4 x3 = __ldcg((const float4*)(pa+12));
                    va[0]=tf32r(x0.x); va[1]=tf32r(x0.y); va[2]=tf32r(x0.z); va[3]=tf32r(x0.w);
                    va[4]=tf32r(x1.x); va[5]=tf32r(x1.y); va[6]=tf32r(x1.z); va[7]=tf32r(x1.w);
                    va[8]=tf32r(x2.x); va[9]=tf32r(x2.y); va[10]=tf32r(x2.z); va[11]=tf32r(x2.w);
                    va[12]=tf32r(x3.x); va[13]=tf32r(x3.y); va[14]=tf32r(x3.z); va[15]=tf32r(x3.w);
                    const float* pb = g_W2c + (size_t)(kt*64 + bk2)*LAT + n0 + bn8;
                    vb0 = *(const float4*)pb; vb1 = *(const float4*)(pb+4);
                };
                auto STS = [&](int c){
                    stageA64(Asb[c], am, subs, kk0s, va);
                    float* qd = Bsb[c] + bk2*36 + bn8;
                    *(float4*)qd = vb0; *(float4*)(qd+4) = vb1;
                };
                LDG(0); STS(0); LDG(1); __syncthreads();
                for (int kt = 0; kt < 16; kt++){
                    const int c = kt & 1;
                    if (kt+1 < 16) STS(c^1);
                    if (kt+2 < 16) LDG(kt+2);
                    compute64(Asb[c], Bsb[c], wm, wn, g, t4, d);
                    __syncthreads();
                }
                #pragma unroll
                for (int mi = 0; mi < 2; mi++){
                    const int r0 = m0 + wm*32 + mi*16 + g;
                    const int c  = n0 + wn*8 + t4*2;
                    const float c0 = b2[c], c1 = b2[c+1];
                    #pragma unroll
                    for (int hh = 0; hh < 2; hh++){
                        const int r = r0 + hh*8;
                        const float h = data[(size_t)(t*BATCH + r)*DSTRIDE + DIN] * (1.0f/3.0f);
                        float2 bb = __ldcg((const float2*)&base[(size_t)r*LAT + c]);
                        __stcg((float2*)&g_Y[(size_t)r*LAT + c],
                               make_float2(bb.x + (d[mi][hh*2+0] + c0)*h,
                                           bb.y + (d[mi][hh*2+1] + c1)*h));
                    }
                }
            }
            gridbar(b);
            base = g_Y;
        }

        // ===== phase D: GRU full-K gate streams; tiles = (3J/32) x 4, KT=20 =====
        {
            const int CT = 3*J/32;
            const int ntiles = CT*4;
            for (int tile = b; tile < ntiles; tile += NB){
                const int ct = tile % CT;
                const int m0 = ((tile / CT) & 3)*64;
                const int c0 = ct*32;
                const int gate = c0 / J, j0c = c0 - gate*J;
                const int wcol = gate*1024 + j0c;

                float dx[2][4] = {{0.f,0.f,0.f,0.f},{0.f,0.f,0.f,0.f}};
                float dh[2][4] = {{0.f,0.f,0.f,0.f},{0.f,0.f,0.f,0.f}};
                float va[16]; float4 vb0, vb1;
                auto LDG = [&](int kt){
                    if (kt < 4){
                        const float* pa = data + (size_t)(t*BATCH + m0 + am)*DSTRIDE + kt*64 + lane4*16;
                        #pragma unroll
                        for (int j = 0; j < 16; j++) va[j] = tf32r(pa[j]);
                        const float* pb = g_WihTc + (size_t)(kt*64 + bk2)*JC + wcol + bn8;
                        vb0 = *(const float4*)pb; vb1 = *(const float4*)(pb+4);
                    } else {
                        const float* src = (kt < 12) ? g_Y : Sr;
                        const int kc = (kt < 12) ? (kt-4)*64 : (kt-12)*64;
                        const float* pa = src + (size_t)(m0+am)*LAT + kc + lane4*16;
                        float4 x0 = __ldcg((const float4*)pa);
                        float4 x1 = __ldcg((const float4*)(pa+4));
                        float4 x2 = __ldcg((const float4*)(pa+8));
                        float4 x3 = __ldcg((const float4*)(pa+12));
                        va[0]=tf32r(x0.x); va[1]=tf32r(x0.y); va[2]=tf32r(x0.z); va[3]=tf32r(x0.w);
                        va[4]=tf32r(x1.x); va[5]=tf32r(x1.y); va[6]=tf32r(x1.z); va[7]=tf32r(x1.w);
                        va[8]=tf32r(x2.x); va[9]=tf32r(x2.y); va[10]=tf32r(x2.z); va[11]=tf32r(x2.w);
                        va[12]=tf32r(x3.x); va[13]=tf32r(x3.y); va[14]=tf32r(x3.z); va[15]=tf32r(x3.w);
                        const float* pb = g_WhhTc + (size_t)((kt-4)*64 + bk2)*JC + wcol + bn8;
                        vb0 = *(const float4*)pb; vb1 = *(const float4*)(pb+4);
                    }
                };
                auto STS = [&](int c){
                    stageA64(Asb[c], am, subs, kk0s, va);
                    float* qd = Bsb[c] + bk2*36 + bn8;
                    *(float4*)qd = vb0; *(float4*)(qd+4) = vb1;
                };
                LDG(0); STS(0); LDG(1); __syncthreads();
                for (int kt = 0; kt < 20; kt++){
                    const int c = kt & 1;
                    if (kt+1 < 20) STS(c^1);
                    if (kt+2 < 20) LDG(kt+2);
                    if (kt < 4) compute64(Asb[c], Bsb[c], wm, wn, g, t4, dx);
                    else        compute64(Asb[c], Bsb[c], wm, wn, g, t4, dh);
                    __syncthreads();
                }
                const int jg = j0c + wn*8 + t4*2;
                #pragma unroll
                for (int mi = 0; mi < 2; mi++){
                    const int r0 = m0 + wm*32 + mi*16 + g;
                    #pragma unroll
                    for (int hh = 0; hh < 2; hh++){
                        const int r = r0 + hh*8;
                        const size_t off = (size_t)r*HID + jg;
                        const float x0 = dx[mi][hh*2+0], x1 = dx[mi][hh*2+1];
                        const float h0 = dh[mi][hh*2+0], h1 = dh[mi][hh*2+1];
                        if (gate == 0)      __stcg((float2*)&g_Gp[0][off], make_float2(x0+h0, x1+h1));
                        else if (gate == 1) __stcg((float2*)&g_Gp[1][off], make_float2(x0+h0, x1+h1));
                        else {
                            __stcg((float2*)&g_Gp[2][off], make_float2(x0, x1));
                            __stcg((float2*)&g_Gp[3][off], make_float2(h0, h1));
                        }
                    }
                }
                __syncthreads();
            }
        }
        gridbar(b);

        // ===== phase E: gates =====
        {
            const int tot = BATCH*J/2;
            const bool last = (t == L_SEQ-1);
            for (int idx = b*256 + tid; idx < tot; idx += NB*256){
                const int e = idx*2;
                const int i = e / J, j = e - (e/J)*J;
                const size_t off = (size_t)i*HID + j;
                float2 rv = __ldcg((const float2*)&g_Gp[0][off]);
                float2 zv = __ldcg((const float2*)&g_Gp[1][off]);
                float2 xv = __ldcg((const float2*)&g_Gp[2][off]);
                float2 hv = __ldcg((const float2*)&g_Gp[3][off]);
                float rs[2] = { rv.x, rv.y }, zs[2] = { zv.x, zv.y };
                float xs[2] = { xv.x, xv.y }, hs[2] = { hv.x, hv.y };
                #pragma unroll
                for (int p = 0; p < 2; p++){
                    const int jj = j + p;
                    float rg = fsigmoid(rs[p] + bih[jj] + bhh[jj]);
                    float zg = fsigmoid(zs[p] + bih[HID+jj] + bhh[HID+jj]);
                    float ng = ftanh((xs[p] + bih[2*HID+jj]) + rg*(hs[p] + bhh[2*HID+jj]));
                    float hvv = (jj < LAT) ? __ldcg(&g_Y[(size_t)i*LAT + jj])
                                           : __ldcg(&Sr[(size_t)i*LAT + jj - LAT]);
                    float v = (1.0f - zg)*ng + zg*hvv;
                    if (jj < LAT){
                        out[(size_t)(t*BATCH + i)*LAT + jj] = v;
                        __stcg(&Sw[(size_t)i*LAT + jj], v);
                    }
                    if (last) out[OUT2_OFF + (size_t)i*HID + jj] = v;
                }
            }
        }
        gridbar(b);
    }
}

extern "C" void kernel_launch(void* const* d_in, const int* in_sizes, int n_in,
                              void* d_out, int out_size)
{
    const float* data = (const float*)d_in[0];
    const float* w1   = (const float*)d_in[1];
    const float* b1   = (const float*)d_in[2];
    const float* w2   = (const float*)d_in[3];
    const float* b2   = (const float*)d_in[4];
    const float* wih  = (const float*)d_in[5];
    const float* bih  = (const float*)d_in[6];
    const float* whh  = (const float*)d_in[7];
    const float* bhh  = (const float*)d_in[8];
    float* out = (float*)d_out;

    float *W1c, *W2c, *WihT, *WhhT;
    cudaGetSymbolAddress((void**)&W1c, g_W1c);
    cudaGetSymbolAddress((void**)&W2c, g_W2c);
    cudaGetSymbolAddress((void**)&WihT, g_WihTc);
    cudaGetSymbolAddress((void**)&WhhT, g_WhhTc);

    static bool attr_set = false;
    if (!attr_set){
        cudaFuncSetAttribute(k_main, cudaFuncAttributeMaxDynamicSharedMemorySize,
                             SMEM_FLOATS*(int)sizeof(float));
        attr_set = true;
    }

    k_cvt4<<<(LAT*HODE/4 + 255)/256, 256>>>(w1, W1c, LAT*HODE/4);
    k_cvt4<<<(HODE*LAT/4 + 255)/256, 256>>>(w2, W2c, HODE*LAT/4);
    k_transpose<<<dim3(JC/32, DIN/32), 256>>>(wih, DIN, WihT);
    k_transpose<<<dim3(JC/32, HID/32), 256>>>(whh, HID, WhhT);

    k_main<<<NB, 256, SMEM_FLOATS*(int)sizeof(float)>>>(data, b1, b2, bih, bhh, out);

    (void)in_sizes; (void)n_in; (void)out_size;
}

// round 14
// speedup vs baseline: 2.2274x; 2.2274x over previous
#include <cuda_runtime.h>
#include <cstdint>

#define L_SEQ  50
#define BATCH  256
#define DIN    256
#define LAT    512
#define HODE   1024
#define HID    1024
#define DSTRIDE 257
#define JC     3072
#define OUT2_OFF (L_SEQ*BATCH*LAT)
#define NB     256

// ---- persistent scratch ----
__device__ float g_S0[BATCH*LAT];
__device__ float g_S1[BATCH*LAT];
__device__ float g_Y [BATCH*LAT];
__device__ float g_P [4][BATCH*HODE];     // mlp1 split-K partials
__device__ float g_Q [8][BATCH*LAT];      // mlp2 split-K partials
__device__ float g_Gp[5][BATCH*JC];       // gru partials per K-slice, gate-major
__device__ float g_W1c [LAT*HODE];        // tf32-rounded weights (immutable -> L1-cached)
__device__ float g_W2c [HODE*LAT];
__device__ float g_WihTc[DIN*JC];
__device__ float g_WhhTc[HID*JC];

// ---- two-level tree barrier (monotonic, replay-safe, acq/rel only -> no L1 flush) ----
__device__ unsigned g_c1[16*32];          // one counter per 128B line
__device__ unsigned g_c0;
__device__ unsigned g_sense;

__device__ __forceinline__ void gridbar(int b){
    __syncthreads();
    if (threadIdx.x == 0){
        unsigned s;
        asm volatile("ld.acquire.gpu.u32 %0, [%1];" : "=r"(s) : "l"(&g_sense) : "memory");
        unsigned o1;
        asm volatile("atom.add.acq_rel.gpu.u32 %0, [%1], 1;"
                     : "=r"(o1) : "l"(&g_c1[(b>>4)*32]) : "memory");
        if ((o1 & 15u) == 15u){
            unsigned o0;
            asm volatile("atom.add.acq_rel.gpu.u32 %0, [%1], 1;"
                         : "=r"(o0) : "l"(&g_c0) : "memory");
            if ((o0 & 15u) == 15u){
                asm volatile("st.release.gpu.u32 [%0], %1;" :: "l"(&g_sense), "r"(s+1u) : "memory");
            } else {
                unsigned v;
                do { asm volatile("ld.acquire.gpu.u32 %0, [%1];" : "=r"(v) : "l"(&g_sense) : "memory"); } while (v == s);
            }
        } else {
            unsigned v;
            do { asm volatile("ld.acquire.gpu.u32 %0, [%1];" : "=r"(v) : "l"(&g_sense) : "memory"); } while (v == s);
        }
    }
    __syncthreads();
}

__device__ __forceinline__ float tf32r(float x){
    uint32_t u; asm("cvt.rna.tf32.f32 %0, %1;" : "=r"(u) : "f"(x));
    return __uint_as_float(u);
}
__device__ __forceinline__ float fsigmoid(float x){ return 1.0f/(1.0f + __expf(-x)); }
__device__ __forceinline__ float ftanh(float x){ return 1.0f - 2.0f/(__expf(2.0f*x) + 1.0f); }

__device__ __forceinline__ void mma8(float (&d)[4], const uint32_t (&a)[4], const uint32_t (&b)[2]){
    asm volatile("mma.sync.aligned.m16n8k8.row.col.f32.tf32.tf32.f32 "
        "{%0,%1,%2,%3}, {%4,%5,%6,%7}, {%8,%9}, {%0,%1,%2,%3};"
        : "+f"(d[0]),"+f"(d[1]),"+f"(d[2]),"+f"(d[3])
        : "r"(a[0]),"r"(a[1]),"r"(a[2]),"r"(a[3]), "r"(b[0]),"r"(b[1]));
}

// A stored k-permuted: col = (k&3)*8 + (k>>2). Load 8 LDS.128 -> all fragments.
__device__ __forceinline__ void load_afrag(const float (*As)[36], int wm, int g, int t4,
                                           float (&Ar)[4][8])
{
    #pragma unroll
    for (int rr = 0; rr < 4; rr++){
        const int row = wm*32 + rr*8 + g;
        float4 h0 = *(const float4*)&As[row][t4*8];
        float4 h1 = *(const float4*)&As[row][t4*8+4];
        Ar[rr][0]=h0.x; Ar[rr][1]=h0.y; Ar[rr][2]=h0.z; Ar[rr][3]=h0.w;
        Ar[rr][4]=h1.x; Ar[rr][5]=h1.y; Ar[rr][6]=h1.z; Ar[rr][7]=h1.w;
    }
}

__device__ __forceinline__ void mma_tile_perm(const float (&Ar)[4][8], const float (*Bs)[72],
                                              int wn, int g, int t4, float (&d)[2][2][4])
{
    #pragma unroll
    for (int ks = 0; ks < 4; ks++){
        const int k8 = ks*8;
        uint32_t b[2][2];
        #pragma unroll
        for (int ni = 0; ni < 2; ni++){
            const int nc = wn*16 + ni*8 + g;
            b[ni][0] = __float_as_uint(Bs[k8+t4  ][nc]);
            b[ni][1] = __float_as_uint(Bs[k8+t4+4][nc]);
        }
        #pragma unroll
        for (int mi = 0; mi < 2; mi++){
            uint32_t a[4] = { __float_as_uint(Ar[2*mi  ][2*ks  ]),
                              __float_as_uint(Ar[2*mi+1][2*ks  ]),
                              __float_as_uint(Ar[2*mi  ][2*ks+1]),
                              __float_as_uint(Ar[2*mi+1][2*ks+1]) };
            #pragma unroll
            for (int ni = 0; ni < 2; ni++)
                mma8(d[mi][ni], a, b[ni]);
        }
    }
}

// stage 8 values (global-k contiguous at local base q*8) into permuted row am
__device__ __forceinline__ void stageA(float (*As)[36], int am, int q, const float* v8){
    #pragma unroll
    for (int j = 0; j < 8; j++)
        As[am][(j&3)*8 + 2*q + (j>>2)] = v8[j];
}

__device__ __forceinline__ void epi_store_cg(float* Out, int ld, int m0, int n0,
                                             int wm, int wn, int g, int t4, float (&d)[2][2][4])
{
    #pragma unroll
    for (int mi = 0; mi < 2; mi++){
        const int r0 = m0 + wm*32 + mi*16 + g;
        #pragma unroll
        for (int ni = 0; ni < 2; ni++){
            const int c = n0 + wn*16 + ni*8 + t4*2;
            __stcg((float2*)&Out[(size_t)r0*ld + c],     make_float2(d[mi][ni][0], d[mi][ni][1]));
            __stcg((float2*)&Out[(size_t)(r0+8)*ld + c], make_float2(d[mi][ni][2], d[mi][ni][3]));
        }
    }
}

// ---- setup kernels ----
__global__ __launch_bounds__(256) void k_cvt4(const float* __restrict__ in,
                                              float* __restrict__ out, int n4)
{
    int i = blockIdx.x*256 + threadIdx.x;
    if (i >= n4) return;
    float4 v = *(const float4*)&in[i*4];
    v.x = tf32r(v.x); v.y = tf32r(v.y); v.z = tf32r(v.z); v.w = tf32r(v.w);
    *(float4*)&out[i*4] = v;
}

__global__ __launch_bounds__(256) void k_transpose(const float* __restrict__ W, int K,
                                                   float* __restrict__ WT)
{
    __shared__ float tile[32][33];
    const int j0 = blockIdx.x*32, k0 = blockIdx.y*32;
    const int r = threadIdx.x >> 3, c4 = (threadIdx.x & 7)*4;
    float4 v = *(const float4*)&W[(size_t)(j0+r)*K + k0 + c4];
    tile[r][c4+0]=v.x; tile[r][c4+1]=v.y; tile[r][c4+2]=v.z; tile[r][c4+3]=v.w;
    __syncthreads();
    float4 o = make_float4(tf32r(tile[c4+0][r]), tf32r(tile[c4+1][r]),
                           tf32r(tile[c4+2][r]), tf32r(tile[c4+3][r]));
    *(float4*)&WT[(size_t)(k0+r)*JC + j0 + c4] = o;
}

// ==================== THE persistent kernel ====================
__global__ __launch_bounds__(256, 2) void k_main(const float* __restrict__ data,
                                                 const float* __restrict__ b1,
                                                 const float* __restrict__ b2,
                                                 const float* __restrict__ bih,
                                                 const float* __restrict__ bhh,
                                                 float* __restrict__ out)
{
    __shared__ float As[2][64][36];
    __shared__ float Bs[2][32][72];
    const int tid = threadIdx.x;
    const int b   = blockIdx.x;
    const int lane = tid & 31, warp = tid >> 5;
    const int wm = warp >> 2, wn = warp & 3;
    const int g = lane >> 2, t4 = lane & 3;
    const int am = tid >> 2, q = tid & 3, q8 = q*8;    // A staging
    const int bk = tid >> 3, bnq = (tid & 7)*8;        // B staging

    // zero initial state
    {
        const int e0 = b*(BATCH*LAT/NB) + tid*2;
        __stcg((float2*)&g_S0[e0], make_float2(0.f, 0.f));
    }
    gridbar(b);

    for (int t = 0; t < L_SEQ; t++){
        float* Sr = (t & 1) ? g_S1 : g_S0;
        float* Sw = (t & 1) ? g_S0 : g_S1;
        const int J = (t == L_SEQ-1) ? HID : LAT;
        const float* base = Sr;

        for (int s = 0; s < 3; s++){
            // ---------- phase A: mlp1 partials, tiles (16 n, 4 m, 4 z), KT=4 ----------
            {
                const int n0 = (b & 15)*64, m0 = ((b>>4)&3)*64, z = b>>6;
                const int kb = z*128;
                float d[2][2][4];
                #pragma unroll
                for (int mi=0;mi<2;mi++) for (int ni=0;ni<2;ni++) for (int p=0;p<4;p++) d[mi][ni][p]=0.f;

                float va[8]; float4 rb0, rb1;
                auto ldg = [&](int kt){
                    const float* pa = &base[(size_t)(m0+am)*LAT + kb + kt*32 + q8];
                    float4 v0 = __ldcg((const float4*)pa);
                    float4 v1 = __ldcg((const float4*)(pa+4));
                    va[0]=tf32r(v0.x); va[1]=tf32r(v0.y); va[2]=tf32r(v0.z); va[3]=tf32r(v0.w);
                    va[4]=tf32r(v1.x); va[5]=tf32r(v1.y); va[6]=tf32r(v1.z); va[7]=tf32r(v1.w);
                    const float* pb = &g_W1c[(size_t)(kb + kt*32 + bk)*HODE + n0 + bnq];
                    rb0 = *(const float4*)pb; rb1 = *(const float4*)(pb+4);
                };
                auto sts = [&](int c){
                    stageA(As[c], am, q, va);
                    *(float4*)&Bs[c][bk][bnq] = rb0; *(float4*)&Bs[c][bk][bnq+4] = rb1;
                };
                ldg(0); sts(0); __syncthreads();
                for (int kt = 0; kt < 4; kt++){
                    const int c = kt & 1;
                    if (kt < 3) ldg(kt+1);
                    float Ar[4][8];
                    load_afrag(As[c], wm, g, t4, Ar);
                    mma_tile_perm(Ar, Bs[c], wn, g, t4, d);
                    if (kt < 3) sts(c^1);
                    __syncthreads();
                }
                epi_store_cg(g_P[z], HODE, m0, n0, wm, wn, g, t4, d);
            }
            gridbar(b);

            // ---------- phase B: mlp2 partials, tiles (8 n, 4 m, 8 z), KT=4 ----------
            {
                const int n0 = (b & 7)*64, m0 = ((b>>3)&3)*64, z = b>>5;
                const int kb = z*128;
                float d[2][2][4];
                #pragma unroll
                for (int mi=0;mi<2;mi++) for (int ni=0;ni<2;ni++) for (int p=0;p<4;p++) d[mi][ni][p]=0.f;

                float va[8]; float4 rb0, rb1;
                auto ldg = [&](int kt){
                    const size_t off = (size_t)(m0+am)*HODE + kb + kt*32 + q8;
                    float4 a0 = __ldcg((const float4*)&g_P[0][off]);
                    float4 a1 = __ldcg((const float4*)&g_P[1][off]);
                    float4 a2 = __ldcg((const float4*)&g_P[2][off]);
                    float4 a3 = __ldcg((const float4*)&g_P[3][off]);
                    float4 d0 = __ldcg((const float4*)&g_P[0][off+4]);
                    float4 d1 = __ldcg((const float4*)&g_P[1][off+4]);
                    float4 d2 = __ldcg((const float4*)&g_P[2][off+4]);
                    float4 d3 = __ldcg((const float4*)&g_P[3][off+4]);
                    float4 c0 = *(const float4*)&b1[kb + kt*32 + q8];
                    float4 c1 = *(const float4*)&b1[kb + kt*32 + q8 + 4];
                    va[0]=tf32r(ftanh(a0.x+a1.x+a2.x+a3.x+c0.x));
                    va[1]=tf32r(ftanh(a0.y+a1.y+a2.y+a3.y+c0.y));
                    va[2]=tf32r(ftanh(a0.z+a1.z+a2.z+a3.z+c0.z));
                    va[3]=tf32r(ftanh(a0.w+a1.w+a2.w+a3.w+c0.w));
                    va[4]=tf32r(ftanh(d0.x+d1.x+d2.x+d3.x+c1.x));
                    va[5]=tf32r(ftanh(d0.y+d1.y+d2.y+d3.y+c1.y));
                    va[6]=tf32r(ftanh(d0.z+d1.z+d2.z+d3.z+c1.z));
                    va[7]=tf32r(ftanh(d0.w+d1.w+d2.w+d3.w+c1.w));
                    const float* pb = &g_W2c[(size_t)(kb + kt*32 + bk)*LAT + n0 + bnq];
                    rb0 = *(const float4*)pb; rb1 = *(const float4*)(pb+4);
                };
                auto sts = [&](int c){
                    stageA(As[c], am, q, va);
                    *(float4*)&Bs[c][bk][bnq] = rb0; *(float4*)&Bs[c][bk][bnq+4] = rb1;
                };
                ldg(0); sts(0); __syncthreads();
                for (int kt = 0; kt < 4; kt++){
                    const int c = kt & 1;
                    if (kt < 3) ldg(kt+1);
                    float Ar[4][8];
                    load_afrag(As[c], wm, g, t4, Ar);
                    mma_tile_perm(Ar, Bs[c], wn, g, t4, d);
                    if (kt < 3) sts(c^1);
                    __syncthreads();
                }
                epi_store_cg(g_Q[z], LAT, m0, n0, wm, wn, g, t4, d);
            }
            gridbar(b);

            // ---------- phase C: euler combine ----------
            {
                const int e = (b*256 + tid)*2;
                const int m = e / LAT, n = e % LAT;
                const float h = data[(size_t)(t*BATCH + m)*DSTRIDE + DIN] * (1.0f/3.0f);
                float2 bb = __ldcg((const float2*)&base[e]);
                float2 cc = *(const float2*)&b2[n];
                float sx = cc.x, sy = cc.y;
                #pragma unroll
                for (int z = 0; z < 8; z++){
                    float2 qv = __ldcg((const float2*)&g_Q[z][e]);
                    sx += qv.x; sy += qv.y;
                }
                __stcg((float2*)&g_Y[e], make_float2(bb.x + sx*h, bb.y + sy*h));
            }
            gridbar(b);
            base = g_Y;
        }

        // ---------- phase D: GRU partials; 5 uniform K-slices of 256, KT=8 ----------
        {
            const int CT = 3*J/64;
            const int ntiles = CT*4*5;
            const int NC3 = 3*J;
            for (int tile = b; tile < ntiles; tile += NB){
                const int ct = tile % CT;
                const int m0 = ((tile / CT) & 3)*64;
                const int z  = tile / (CT*4);
                const int c0 = ct*64;
                const int gate = c0 / J, j0 = c0 - gate*J;
                const int wcol = gate*1024 + j0;
                const float* WT = (z == 0) ? g_WihTc : g_WhhTc;
                const int krow0 = (z == 0) ? 0 : (z-1)*256;
                const float* Asrc = (z <= 2) ? g_Y : Sr;       // z==0 unused
                const int kc0 = (z == 0) ? 0 : ((z == 1 || z == 3) ? 0 : 256);

                float d[2][2][4];
                #pragma unroll
                for (int mi=0;mi<2;mi++) for (int ni=0;ni<2;ni++) for (int p=0;p<4;p++) d[mi][ni][p]=0.f;

                float va[8]; float4 rb0, rb1;
                auto ldg = [&](int kt){
                    if (z == 0){
                        const float* pa = &data[(size_t)(t*BATCH + m0 + am)*DSTRIDE + kt*32 + q8];
                        #pragma unroll
                        for (int j = 0; j < 8; j++) va[j] = tf32r(pa[j]);
                    } else {
                        const float* pa = &Asrc[(size_t)(m0+am)*LAT + kc0 + kt*32 + q8];
                        float4 v0 = __ldcg((const float4*)pa);
                        float4 v1 = __ldcg((const float4*)(pa+4));
                        va[0]=tf32r(v0.x); va[1]=tf32r(v0.y); va[2]=tf32r(v0.z); va[3]=tf32r(v0.w);
                        va[4]=tf32r(v1.x); va[5]=tf32r(v1.y); va[6]=tf32r(v1.z); va[7]=tf32r(v1.w);
                    }
                    const float* pb = &WT[(size_t)(krow0 + kt*32 + bk)*JC + wcol + bnq];
                    rb0 = *(const float4*)pb; rb1 = *(const float4*)(pb+4);
                };
                auto sts = [&](int c){
                    stageA(As[c], am, q, va);
                    *(float4*)&Bs[c][bk][bnq] = rb0; *(float4*)&Bs[c][bk][bnq+4] = rb1;
                };
                ldg(0); sts(0); __syncthreads();
                for (int kt = 0; kt < 8; kt++){
                    const int c = kt & 1;
                    if (kt < 7) ldg(kt+1);
                    float Ar[4][8];
                    load_afrag(As[c], wm, g, t4, Ar);
                    mma_tile_perm(Ar, Bs[c], wn, g, t4, d);
                    if (kt < 7) sts(c^1);
                    __syncthreads();
                }
                epi_store_cg(g_Gp[z], NC3, m0, c0, wm, wn, g, t4, d);
                __syncthreads();
            }
        }
        gridbar(b);

        // ---------- phase E: gates ----------
        {
            const int tot = BATCH*J/2;
            const int NC3 = 3*J;
            const bool last = (t == L_SEQ-1);
            for (int idx = b*256 + tid; idx < tot; idx += NB*256){
                const int e = idx*2;
                const int i = e / J, j = e - (e/J)*J;
                const size_t gb = (size_t)i*NC3;
                float rs0=0.f, rs1=0.f, zs0=0.f, zs1=0.f, hs0=0.f, hs1=0.f;
                #pragma unroll
                for (int z = 1; z < 5; z++){
                    float2 rv = __ldcg((const float2*)&g_Gp[z][gb + j]);
                    float2 zv = __ldcg((const float2*)&g_Gp[z][gb + J + j]);
                    float2 hv = __ldcg((const float2*)&g_Gp[z][gb + 2*J + j]);
                    rs0 += rv.x; rs1 += rv.y;  zs0 += zv.x; zs1 += zv.y;
                    hs0 += hv.x; hs1 += hv.y;
                }
                {
                    float2 rv = __ldcg((const float2*)&g_Gp[0][gb + j]);
                    float2 zv = __ldcg((const float2*)&g_Gp[0][gb + J + j]);
                    rs0 += rv.x; rs1 += rv.y;  zs0 += zv.x; zs1 += zv.y;
                }
                float2 xv = __ldcg((const float2*)&g_Gp[0][gb + 2*J + j]);
                float rs[2] = { rs0, rs1 }, zs[2] = { zs0, zs1 };
                float xs[2] = { xv.x, xv.y }, hs[2] = { hs0, hs1 };
                #pragma unroll
                for (int p = 0; p < 2; p++){
                    const int jj = j + p;
                    float rg = fsigmoid(rs[p] + bih[jj] + bhh[jj]);
                    float zg = fsigmoid(zs[p] + bih[HID+jj] + bhh[HID+jj]);
                    float ng = ftanh((xs[p] + bih[2*HID+jj]) + rg*(hs[p] + bhh[2*HID+jj]));
                    float hv = (jj < LAT) ? __ldcg(&g_Y[(size_t)i*LAT + jj])
                                          : __ldcg(&Sr[(size_t)i*LAT + jj - LAT]);
                    float v = (1.0f - zg)*ng + zg*hv;
                    if (jj < LAT){
                        out[(size_t)(t*BATCH + i)*LAT + jj] = v;
                        __stcg(&Sw[(size_t)i*LAT + jj], v);
                    }
                    if (last) out[OUT2_OFF + (size_t)i*HID + jj] = v;
                }
            }
        }
        gridbar(b);
    }
}

extern "C" void kernel_launch(void* const* d_in, const int* in_sizes, int n_in,
                              void* d_out, int out_size)
{
    const float* data = (const float*)d_in[0];
    const float* w1   = (const float*)d_in[1];
    const float* b1   = (const float*)d_in[2];
    const float* w2   = (const float*)d_in[3];
    const float* b2   = (const float*)d_in[4];
    const float* wih  = (const float*)d_in[5];
    const float* bih  = (const float*)d_in[6];
    const float* whh  = (const float*)d_in[7];
    const float* bhh  = (const float*)d_in[8];
    float* out = (float*)d_out;

    float *W1c, *W2c, *WihT, *WhhT;
    cudaGetSymbolAddress((void**)&W1c, g_W1c);
    cudaGetSymbolAddress((void**)&W2c, g_W2c);
    cudaGetSymbolAddress((void**)&WihT, g_WihTc);
    cudaGetSymbolAddress((void**)&WhhT, g_WhhTc);

    k_cvt4<<<(LAT*HODE/4 + 255)/256, 256>>>(w1, W1c, LAT*HODE/4);
    k_cvt4<<<(HODE*LAT/4 + 255)/256, 256>>>(w2, W2c, HODE*LAT/4);
    k_transpose<<<dim3(JC/32, DIN/32), 256>>>(wih, DIN, WihT);
    k_transpose<<<dim3(JC/32, HID/32), 256>>>(whh, HID, WhhT);

    k_main<<<NB, 256>>>(data, b1, b2, bih, bhh, out);

    (void)in_sizes; (void)n_in; (void)out_size;
}

// round 15
// speedup vs baseline: 2.5536x; 1.1464x over previous
#include <cuda_runtime.h>
#include <cstdint>

#define L_SEQ  50
#define BATCH  256
#define DIN    256
#define LAT    512
#define HODE   1024
#define HID    1024
#define DSTRIDE 257
#define JC     3072
#define OUT2_OFF (L_SEQ*BATCH*LAT)
#define NB     256

// ---- persistent scratch ----
__device__ float g_S0[BATCH*LAT];
__device__ float g_S1[BATCH*LAT];
__device__ float g_Ya[BATCH*LAT];
__device__ float g_Yb[BATCH*LAT];
__device__ float g_P [4][BATCH*HODE];     // mlp1 split-K partials
__device__ float g_Gp[5][BATCH*JC];       // gru partials per K-slice, gate-major
__device__ float g_W1c [LAT*HODE];        // tf32-rounded weights (immutable -> L1-cached)
__device__ float g_W2c [HODE*LAT];
__device__ float g_WihTc[DIN*JC];
__device__ float g_WhhTc[HID*JC];

// ---- flat, launch-idempotent grid barrier (sense-reversal, acq/rel, no fences) ----
__device__ unsigned g_cnt = 0;
__device__ unsigned g_sense = 0;

__device__ __forceinline__ void gridbar(){
    __syncthreads();
    if (threadIdx.x == 0){
        unsigned s;
        asm volatile("ld.acquire.gpu.u32 %0, [%1];" : "=r"(s) : "l"(&g_sense) : "memory");
        unsigned old;
        asm volatile("atom.add.acq_rel.gpu.u32 %0, [%1], 1;"
                     : "=r"(old) : "l"(&g_cnt) : "memory");
        if (old == NB-1u){
            asm volatile("st.relaxed.gpu.u32 [%0], %1;" :: "l"(&g_cnt), "r"(0u) : "memory");
            asm volatile("st.release.gpu.u32 [%0], %1;" :: "l"(&g_sense), "r"(s+1u) : "memory");
        } else {
            unsigned v;
            do {
                asm volatile("ld.acquire.gpu.u32 %0, [%1];" : "=r"(v) : "l"(&g_sense) : "memory");
            } while (v == s);
        }
    }
    __syncthreads();
}

__device__ __forceinline__ float tf32r(float x){
    uint32_t u; asm("cvt.rna.tf32.f32 %0, %1;" : "=r"(u) : "f"(x));
    return __uint_as_float(u);
}
__device__ __forceinline__ float fsigmoid(float x){ return 1.0f/(1.0f + __expf(-x)); }
__device__ __forceinline__ float ftanh(float x){ return 1.0f - 2.0f/(__expf(2.0f*x) + 1.0f); }

__device__ __forceinline__ void mma8(float (&d)[4], const uint32_t (&a)[4], const uint32_t (&b)[2]){
    asm volatile("mma.sync.aligned.m16n8k8.row.col.f32.tf32.tf32.f32 "
        "{%0,%1,%2,%3}, {%4,%5,%6,%7}, {%8,%9}, {%0,%1,%2,%3};"
        : "+f"(d[0]),"+f"(d[1]),"+f"(d[2]),"+f"(d[3])
        : "r"(a[0]),"r"(a[1]),"r"(a[2]),"r"(a[3]), "r"(b[0]),"r"(b[1]));
}

// A stored k-permuted: col = (k&3)*8 + (k>>2). Load 8 LDS.128 -> all fragments.
__device__ __forceinline__ void load_afrag(const float (*As)[36], int wm, int g, int t4,
                                           float (&Ar)[4][8])
{
    #pragma unroll
    for (int rr = 0; rr < 4; rr++){
        const int row = wm*32 + rr*8 + g;
        float4 h0 = *(const float4*)&As[row][t4*8];
        float4 h1 = *(const float4*)&As[row][t4*8+4];
        Ar[rr][0]=h0.x; Ar[rr][1]=h0.y; Ar[rr][2]=h0.z; Ar[rr][3]=h0.w;
        Ar[rr][4]=h1.x; Ar[rr][5]=h1.y; Ar[rr][6]=h1.z; Ar[rr][7]=h1.w;
    }
}

__device__ __forceinline__ void mma_tile_perm(const float (&Ar)[4][8], const float (*Bs)[72],
                                              int wn, int g, int t4, float (&d)[2][2][4])
{
    #pragma unroll
    for (int ks = 0; ks < 4; ks++){
        const int k8 = ks*8;
        uint32_t b[2][2];
        #pragma unroll
        for (int ni = 0; ni < 2; ni++){
            const int nc = wn*16 + ni*8 + g;
            b[ni][0] = __float_as_uint(Bs[k8+t4  ][nc]);
            b[ni][1] = __float_as_uint(Bs[k8+t4+4][nc]);
        }
        #pragma unroll
        for (int mi = 0; mi < 2; mi++){
            uint32_t a[4] = { __float_as_uint(Ar[2*mi  ][2*ks  ]),
                              __float_as_uint(Ar[2*mi+1][2*ks  ]),
                              __float_as_uint(Ar[2*mi  ][2*ks+1]),
                              __float_as_uint(Ar[2*mi+1][2*ks+1]) };
            #pragma unroll
            for (int ni = 0; ni < 2; ni++)
                mma8(d[mi][ni], a, b[ni]);
        }
    }
}

// stage 8 values (global-k contiguous at local base q*8) into permuted row am
__device__ __forceinline__ void stageA(float (*As)[36], int am, int q, const float* v8){
    #pragma unroll
    for (int j = 0; j < 8; j++)
        As[am][(j&3)*8 + 2*q + (j>>2)] = v8[j];
}

__device__ __forceinline__ void epi_store_cg(float* Out, int ld, int m0, int n0,
                                             int wm, int wn, int g, int t4, float (&d)[2][2][4])
{
    #pragma unroll
    for (int mi = 0; mi < 2; mi++){
        const int r0 = m0 + wm*32 + mi*16 + g;
        #pragma unroll
        for (int ni = 0; ni < 2; ni++){
            const int c = n0 + wn*16 + ni*8 + t4*2;
            __stcg((float2*)&Out[(size_t)r0*ld + c],     make_float2(d[mi][ni][0], d[mi][ni][1]));
            __stcg((float2*)&Out[(size_t)(r0+8)*ld + c], make_float2(d[mi][ni][2], d[mi][ni][3]));
        }
    }
}

// ---- setup kernels ----
__global__ __launch_bounds__(256) void k_cvt4(const float* __restrict__ in,
                                              float* __restrict__ out, int n4)
{
    int i = blockIdx.x*256 + threadIdx.x;
    if (i >= n4) return;
    float4 v = *(const float4*)&in[i*4];
    v.x = tf32r(v.x); v.y = tf32r(v.y); v.z = tf32r(v.z); v.w = tf32r(v.w);
    *(float4*)&out[i*4] = v;
}

__global__ __launch_bounds__(256) void k_transpose(const float* __restrict__ W, int K,
                                                   float* __restrict__ WT)
{
    __shared__ float tile[32][33];
    const int j0 = blockIdx.x*32, k0 = blockIdx.y*32;
    const int r = threadIdx.x >> 3, c4 = (threadIdx.x & 7)*4;
    float4 v = *(const float4*)&W[(size_t)(j0+r)*K + k0 + c4];
    tile[r][c4+0]=v.x; tile[r][c4+1]=v.y; tile[r][c4+2]=v.z; tile[r][c4+3]=v.w;
    __syncthreads();
    float4 o = make_float4(tf32r(tile[c4+0][r]), tf32r(tile[c4+1][r]),
                           tf32r(tile[c4+2][r]), tf32r(tile[c4+3][r]));
    *(float4*)&WT[(size_t)(k0+r)*JC + j0 + c4] = o;
}

// ==================== THE persistent kernel ====================
__global__ __launch_bounds__(256, 2) void k_main(const float* __restrict__ data,
                                                 const float* __restrict__ b1,
                                                 const float* __restrict__ b2,
                                                 const float* __restrict__ bih,
                                                 const float* __restrict__ bhh,
                                                 float* __restrict__ out)
{
    __shared__ float As[2][64][36];
    __shared__ float Bs[2][32][72];
    const int tid = threadIdx.x;
    const int b   = blockIdx.x;
    const int lane = tid & 31, warp = tid >> 5;
    const int wm = warp >> 2, wn = warp & 3;
    const int g = lane >> 2, t4 = lane & 3;
    const int am = tid >> 2, q = tid & 3, q8 = q*8;    // A staging
    const int bk = tid >> 3, bnq = (tid & 7)*8;        // B staging

    // zero initial state
    {
        const int e0 = b*(BATCH*LAT/NB) + tid*2;
        __stcg((float2*)&g_S0[e0], make_float2(0.f, 0.f));
    }
    gridbar();

    for (int t = 0; t < L_SEQ; t++){
        float* Sr = (t & 1) ? g_S1 : g_S0;
        float* Sw = (t & 1) ? g_S0 : g_S1;
        const int J = (t == L_SEQ-1) ? HID : LAT;
        const float* base = Sr;

        for (int s = 0; s < 3; s++){
            float* ynext = (s == 1) ? g_Yb : g_Ya;

            // ---------- phase A: Yinit + mlp1 partials, tiles (16 n, 4 m, 4 z), KT=4 ----------
            {
                // Yinit: ynext = base + b2*h  (independent of this phase's GEMM)
                {
                    const int e = b*(BATCH*LAT/NB) + tid*2;
                    const int m = e >> 9, n = e & (LAT-1);
                    const float h = data[(size_t)(t*BATCH + m)*DSTRIDE + DIN] * (1.0f/3.0f);
                    float2 bb = __ldcg((const float2*)&base[e]);
                    float2 cc = *(const float2*)&b2[n];
                    __stcg((float2*)&ynext[e], make_float2(bb.x + cc.x*h, bb.y + cc.y*h));
                }

                const int n0 = (b & 15)*64, m0 = ((b>>4)&3)*64, z = b>>6;
                const int kb = z*128;
                float d[2][2][4];
                #pragma unroll
                for (int mi=0;mi<2;mi++) for (int ni=0;ni<2;ni++) for (int p=0;p<4;p++) d[mi][ni][p]=0.f;

                float va[8]; float4 rb0, rb1;
                auto ldg = [&](int kt){
                    const float* pa = &base[(size_t)(m0+am)*LAT + kb + kt*32 + q8];
                    float4 v0 = __ldcg((const float4*)pa);
                    float4 v1 = __ldcg((const float4*)(pa+4));
                    va[0]=tf32r(v0.x); va[1]=tf32r(v0.y); va[2]=tf32r(v0.z); va[3]=tf32r(v0.w);
                    va[4]=tf32r(v1.x); va[5]=tf32r(v1.y); va[6]=tf32r(v1.z); va[7]=tf32r(v1.w);
                    const float* pb = &g_W1c[(size_t)(kb + kt*32 + bk)*HODE + n0 + bnq];
                    rb0 = *(const float4*)pb; rb1 = *(const float4*)(pb+4);
                };
                auto sts = [&](int c){
                    stageA(As[c], am, q, va);
                    *(float4*)&Bs[c][bk][bnq] = rb0; *(float4*)&Bs[c][bk][bnq+4] = rb1;
                };
                ldg(0); sts(0); __syncthreads();
                for (int kt = 0; kt < 4; kt++){
                    const int c = kt & 1;
                    if (kt < 3) ldg(kt+1);
                    float Ar[4][8];
                    load_afrag(As[c], wm, g, t4, Ar);
                    mma_tile_perm(Ar, Bs[c], wn, g, t4, d);
                    if (kt < 3) sts(c^1);
                    __syncthreads();
                }
                epi_store_cg(g_P[z], HODE, m0, n0, wm, wn, g, t4, d);
            }
            gridbar();

            // ---------- phase B: mlp2 partials -> red.add into ynext; tiles (8 n, 4 m, 8 z), KT=4 ----------
            {
                const int n0 = (b & 7)*64, m0 = ((b>>3)&3)*64, z = b>>5;
                const int kb = z*128;
                float d[2][2][4];
                #pragma unroll
                for (int mi=0;mi<2;mi++) for (int ni=0;ni<2;ni++) for (int p=0;p<4;p++) d[mi][ni][p]=0.f;

                float va[8]; float4 rb0, rb1;
                auto ldg = [&](int kt){
                    const size_t off = (size_t)(m0+am)*HODE + kb + kt*32 + q8;
                    float4 a0 = __ldcg((const float4*)&g_P[0][off]);
                    float4 a1 = __ldcg((const float4*)&g_P[1][off]);
                    float4 a2 = __ldcg((const float4*)&g_P[2][off]);
                    float4 a3 = __ldcg((const float4*)&g_P[3][off]);
                    float4 d0 = __ldcg((const float4*)&g_P[0][off+4]);
                    float4 d1 = __ldcg((const float4*)&g_P[1][off+4]);
                    float4 d2 = __ldcg((const float4*)&g_P[2][off+4]);
                    float4 d3 = __ldcg((const float4*)&g_P[3][off+4]);
                    float4 c0 = *(const float4*)&b1[kb + kt*32 + q8];
                    float4 c1 = *(const float4*)&b1[kb + kt*32 + q8 + 4];
                    va[0]=tf32r(ftanh(a0.x+a1.x+a2.x+a3.x+c0.x));
                    va[1]=tf32r(ftanh(a0.y+a1.y+a2.y+a3.y+c0.y));
                    va[2]=tf32r(ftanh(a0.z+a1.z+a2.z+a3.z+c0.z));
                    va[3]=tf32r(ftanh(a0.w+a1.w+a2.w+a3.w+c0.w));
                    va[4]=tf32r(ftanh(d0.x+d1.x+d2.x+d3.x+c1.x));
                    va[5]=tf32r(ftanh(d0.y+d1.y+d2.y+d3.y+c1.y));
                    va[6]=tf32r(ftanh(d0.z+d1.z+d2.z+d3.z+c1.z));
                    va[7]=tf32r(ftanh(d0.w+d1.w+d2.w+d3.w+c1.w));
                    const float* pb = &g_W2c[(size_t)(kb + kt*32 + bk)*LAT + n0 + bnq];
                    rb0 = *(const float4*)pb; rb1 = *(const float4*)(pb+4);
                };
                auto sts = [&](int c){
                    stageA(As[c], am, q, va);
                    *(float4*)&Bs[c][bk][bnq] = rb0; *(float4*)&Bs[c][bk][bnq+4] = rb1;
                };
                ldg(0); sts(0); __syncthreads();
                for (int kt = 0; kt < 4; kt++){
                    const int c = kt & 1;
                    if (kt < 3) ldg(kt+1);
                    float Ar[4][8];
                    load_afrag(As[c], wm, g, t4, Ar);
                    mma_tile_perm(Ar, Bs[c], wn, g, t4, d);
                    if (kt < 3) sts(c^1);
                    __syncthreads();
                }
                // epilogue: ynext += h * acc  (REDG, no return value used)
                #pragma unroll
                for (int mi = 0; mi < 2; mi++){
                    const int r0 = m0 + wm*32 + mi*16 + g;
                    const float h0 = data[(size_t)(t*BATCH + r0)*DSTRIDE + DIN] * (1.0f/3.0f);
                    const float h1 = data[(size_t)(t*BATCH + r0 + 8)*DSTRIDE + DIN] * (1.0f/3.0f);
                    #pragma unroll
                    for (int ni = 0; ni < 2; ni++){
                        const int c = n0 + wn*16 + ni*8 + t4*2;
                        atomicAdd(&ynext[(size_t)r0*LAT + c],       d[mi][ni][0]*h0);
                        atomicAdd(&ynext[(size_t)r0*LAT + c + 1],   d[mi][ni][1]*h0);
                        atomicAdd(&ynext[(size_t)(r0+8)*LAT + c],   d[mi][ni][2]*h1);
                        atomicAdd(&ynext[(size_t)(r0+8)*LAT + c+1], d[mi][ni][3]*h1);
                    }
                }
            }
            gridbar();
            base = ynext;
        }

        // ---------- phase D: GRU partials; 5 uniform K-slices of 256, KT=8 ----------
        {
            const int CT = 3*J/64;
            const int ntiles = CT*4*5;
            const int NC3 = 3*J;
            for (int tile = b; tile < ntiles; tile += NB){
                const int ct = tile % CT;
                const int m0 = ((tile / CT) & 3)*64;
                const int z  = tile / (CT*4);
                const int c0 = ct*64;
                const int gate = c0 / J, j0 = c0 - gate*J;
                const int wcol = gate*1024 + j0;
                const float* WT = (z == 0) ? g_WihTc : g_WhhTc;
                const int krow0 = (z == 0) ? 0 : (z-1)*256;
                const float* Asrc = (z <= 2) ? g_Ya : Sr;      // z==0 unused
                const int kc0 = (z == 0) ? 0 : ((z == 1 || z == 3) ? 0 : 256);

                float d[2][2][4];
                #pragma unroll
                for (int mi=0;mi<2;mi++) for (int ni=0;ni<2;ni++) for (int p=0;p<4;p++) d[mi][ni][p]=0.f;

                float va[8]; float4 rb0, rb1;
                auto ldg = [&](int kt){
                    if (z == 0){
                        const float* pa = &data[(size_t)(t*BATCH + m0 + am)*DSTRIDE + kt*32 + q8];
                        #pragma unroll
                        for (int j = 0; j < 8; j++) va[j] = tf32r(pa[j]);
                    } else {
                        const float* pa = &Asrc[(size_t)(m0+am)*LAT + kc0 + kt*32 + q8];
                        float4 v0 = __ldcg((const float4*)pa);
                        float4 v1 = __ldcg((const float4*)(pa+4));
                        va[0]=tf32r(v0.x); va[1]=tf32r(v0.y); va[2]=tf32r(v0.z); va[3]=tf32r(v0.w);
                        va[4]=tf32r(v1.x); va[5]=tf32r(v1.y); va[6]=tf32r(v1.z); va[7]=tf32r(v1.w);
                    }
                    const float* pb = &WT[(size_t)(krow0 + kt*32 + bk)*JC + wcol + bnq];
                    rb0 = *(const float4*)pb; rb1 = *(const float4*)(pb+4);
                };
                auto sts = [&](int c){
                    stageA(As[c], am, q, va);
                    *(float4*)&Bs[c][bk][bnq] = rb0; *(float4*)&Bs[c][bk][bnq+4] = rb1;
                };
                ldg(0); sts(0); __syncthreads();
                for (int kt = 0; kt < 8; kt++){
                    const int c = kt & 1;
                    if (kt < 7) ldg(kt+1);
                    float Ar[4][8];
                    load_afrag(As[c], wm, g, t4, Ar);
                    mma_tile_perm(Ar, Bs[c], wn, g, t4, d);
                    if (kt < 7) sts(c^1);
                    __syncthreads();
                }
                epi_store_cg(g_Gp[z], NC3, m0, c0, wm, wn, g, t4, d);
                __syncthreads();
            }
        }
        gridbar();

        // ---------- phase E: gates ----------
        {
            const int tot = BATCH*J/2;
            const int NC3 = 3*J;
            const bool last = (t == L_SEQ-1);
            for (int idx = b*256 + tid; idx < tot; idx += NB*256){
                const int e = idx*2;
                const int i = e / J, j = e - (e/J)*J;
                const size_t gb = (size_t)i*NC3;
                float rs0=0.f, rs1=0.f, zs0=0.f, zs1=0.f, hs0=0.f, hs1=0.f;
                #pragma unroll
                for (int z = 1; z < 5; z++){
                    float2 rv = __ldcg((const float2*)&g_Gp[z][gb + j]);
                    float2 zv = __ldcg((const float2*)&g_Gp[z][gb + J + j]);
                    float2 hv = __ldcg((const float2*)&g_Gp[z][gb + 2*J + j]);
                    rs0 += rv.x; rs1 += rv.y;  zs0 += zv.x; zs1 += zv.y;
                    hs0 += hv.x; hs1 += hv.y;
                }
                {
                    float2 rv = __ldcg((const float2*)&g_Gp[0][gb + j]);
                    float2 zv = __ldcg((const float2*)&g_Gp[0][gb + J + j]);
                    rs0 += rv.x; rs1 += rv.y;  zs0 += zv.x; zs1 += zv.y;
                }
                float2 xv = __ldcg((const float2*)&g_Gp[0][gb + 2*J + j]);
                float rs[2] = { rs0, rs1 }, zs[2] = { zs0, zs1 };
                float xs[2] = { xv.x, xv.y }, hs[2] = { hs0, hs1 };
                #pragma unroll
                for (int p = 0; p < 2; p++){
                    const int jj = j + p;
                    float rg = fsigmoid(rs[p] + bih[jj] + bhh[jj]);
                    float zg = fsigmoid(zs[p] + bih[HID+jj] + bhh[HID+jj]);
                    float ng = ftanh((xs[p] + bih[2*HID+jj]) + rg*(hs[p] + bhh[2*HID+jj]));
                    float hv = (jj < LAT) ? __ldcg(&g_Ya[(size_t)i*LAT + jj])
                                          : __ldcg(&Sr[(size_t)i*LAT + jj - LAT]);
                    float v = (1.0f - zg)*ng + zg*hv;
                    if (jj < LAT){
                        out[(size_t)(t*BATCH + i)*LAT + jj] = v;
                        __stcg(&Sw[(size_t)i*LAT + jj], v);
                    }
                    if (last) out[OUT2_OFF + (size_t)i*HID + jj] = v;
                }
            }
        }
        gridbar();
    }
}

extern "C" void kernel_launch(void* const* d_in, const int* in_sizes, int n_in,
                              void* d_out, int out_size)
{
    const float* data = (const float*)d_in[0];
    const float* w1   = (const float*)d_in[1];
    const float* b1   = (const float*)d_in[2];
    const float* w2   = (const float*)d_in[3];
    const float* b2   = (const float*)d_in[4];
    const float* wih  = (const float*)d_in[5];
    const float* bih  = (const float*)d_in[6];
    const float* whh  = (const float*)d_in[7];
    const float* bhh  = (const float*)d_in[8];
    float* out = (float*)d_out;

    float *W1c, *W2c, *WihT, *WhhT;
    cudaGetSymbolAddress((void**)&W1c, g_W1c);
    cudaGetSymbolAddress((void**)&W2c, g_W2c);
    cudaGetSymbolAddress((void**)&WihT, g_WihTc);
    cudaGetSymbolAddress((void**)&WhhT, g_WhhTc);

    k_cvt4<<<(LAT*HODE/4 + 255)/256, 256>>>(w1, W1c, LAT*HODE/4);
    k_cvt4<<<(HODE*LAT/4 + 255)/256, 256>>>(w2, W2c, HODE*LAT/4);
    k_transpose<<<dim3(JC/32, DIN/32), 256>>>(wih, DIN, WihT);
    k_transpose<<<dim3(JC/32, HID/32), 256>>>(whh, HID, WhhT);

    k_main<<<NB, 256>>>(data, b1, b2, bih, bhh, out);

    (void)in_sizes; (void)n_in; (void)out_size;
}